// round 16
// baseline (speedup 1.0000x reference)
#include <cuda_runtime.h>
#include <cuda_bf16.h>

#define N_NODES  100000
#define N_EDGES  3200000
#define N_GRAPHS 512
#define VOCAB    128
#define HID      16
#define LABELS   10
#define POOL_CHUNK 8
#define PAD_LOG2 7
#define PAD      (1 << PAD_LOG2)     // row: [cnt, s0..s126]; capacity 127 >= max deg ~70

#define POOL_THREADS ((N_NODES + POOL_CHUNK - 1) / POOL_CHUNK)          // 12500
#define POOL_BLOCKS  ((POOL_THREADS + 255) / 256)                       // 49

// ---------------- scratch (device globals; zero at load, self-cleaned) -------
__device__ int   g_cnt [N_NODES];            // fill-time counter; zeroed by k_node1
// g_pad row i: element 0 = count (written by k_node1), 1.. = src list
__device__ int   g_pad [(size_t)N_NODES * PAD];
__device__ float g_t1  [VOCAB * HID];        // T1 = emb @ W1
__device__ float g_hws [N_NODES * HID];      // scaled features (gather source)
__device__ float g_acc [N_NODES * HID];      // aggregation result
__device__ float g_gsum[N_GRAPHS * HID];     // zeroed by pool tail
__device__ float g_gcnt[N_GRAPHS];           // zeroed by pool tail
__device__ int   g_done;                     // pool done-counter; reset by tail

__device__ __forceinline__ void red_add_v4(float* addr, float4 v) {
    asm volatile("red.global.add.v4.f32 [%0], {%1,%2,%3,%4};"
                 :: "l"(addr), "f"(v.x), "f"(v.y), "f"(v.z), "f"(v.w)
                 : "memory");
}

// ---------------- K0: adjacency build; block 0 also computes T1 --------------
__global__ void k_fill(const int* __restrict__ src, const int* __restrict__ dst,
                       const float* __restrict__ emb, const float* __restrict__ W1) {
    if (blockIdx.x == 0) {
        __shared__ float sW[HID * HID];
        sW[threadIdx.x] = __ldg(W1 + threadIdx.x);      // blockDim = 256 = HID*HID
        __syncthreads();
        if (threadIdx.x < VOCAB) {
            int t = threadIdx.x;
            float e[HID];
            const float4* ep = (const float4*)(emb + (size_t)t * HID);
#pragma unroll
            for (int q = 0; q < 4; q++) {
                float4 v = __ldg(ep + q);
                e[4*q+0] = v.x; e[4*q+1] = v.y; e[4*q+2] = v.z; e[4*q+3] = v.w;
            }
#pragma unroll
            for (int j = 0; j < HID; j++) {
                float s = 0.0f;
#pragma unroll
                for (int k = 0; k < HID; k++) s = fmaf(e[k], sW[k*HID + j], s);
                g_t1[t * HID + j] = s;
            }
        }
    }
    int e = blockIdx.x * blockDim.x + threadIdx.x;
    if (e >= N_EDGES) return;
    int s = __ldg(src + e);
    int d = __ldg(dst + e);
    int p = atomicAdd(&g_cnt[d], 1);
    if (p < PAD - 1) g_pad[((size_t)d << PAD_LOG2) + 1 + p] = s;
}

// ---------------- K1: hws[i] = dinv_i*T1[x_i]; cnt -> row[0]; zero g_cnt -----
__global__ void k_node1(const int* __restrict__ x) {
    int i = blockIdx.x * blockDim.x + threadIdx.x;
    if (i >= N_NODES) return;
    int deg = __ldg(&g_cnt[i]);
    g_pad[(size_t)i << PAD_LOG2] = deg;                 // read-time counter
    g_cnt[i] = 0;                                       // self-clean for replay
    float dv = rsqrtf((float)(deg + 1));                // +1 self loop
    int xi = __ldg(x + i);
    const float4* tp = (const float4*)(g_t1 + (size_t)xi * HID);
    float4* o = (float4*)(g_hws + (size_t)i * HID);
#pragma unroll
    for (int q = 0; q < 4; q++) {
        float4 v = __ldg(tp + q);
        o[q] = make_float4(v.x * dv, v.y * dv, v.z * dv, v.w * dv);
    }
}

// ---------------- K2/K4: warp-per-node gather (cnt from row[0]) --------------
__global__ void k_gather() {
    int node = (blockIdx.x * blockDim.x + threadIdx.x) >> 5;
    if (node >= N_NODES) return;
    int lane = threadIdx.x & 31;
    int q = lane & 3;                          // quarter of feature row (float4)
    const int* adj = g_pad + ((size_t)node << PAD_LOG2);
    int cnt = min(__ldg(adj), PAD - 1);        // neighbors at adj[1..cnt]

    float4 acc = make_float4(0.f, 0.f, 0.f, 0.f);
    int p = (lane >> 2) + 1;
    int s_cur = (p <= cnt) ? __ldg(adj + p) : 0;
    while (p <= cnt) {
        int pn = p + 8;
        int s_nxt = (pn <= cnt) ? __ldg(adj + pn) : 0;   // prefetch next index
        float4 v = __ldg((const float4*)(g_hws + (size_t)s_cur * HID) + q);
        acc.x += v.x; acc.y += v.y; acc.z += v.z; acc.w += v.w;
        p = pn; s_cur = s_nxt;
    }
#pragma unroll
    for (int off = 4; off < 32; off <<= 1) {
        acc.x += __shfl_xor_sync(0xffffffffu, acc.x, off);
        acc.y += __shfl_xor_sync(0xffffffffu, acc.y, off);
        acc.z += __shfl_xor_sync(0xffffffffu, acc.z, off);
        acc.w += __shfl_xor_sync(0xffffffffu, acc.w, off);
    }
    if (lane < 4) {                            // lane == q
        float4 self = __ldg((const float4*)(g_hws + (size_t)node * HID) + lane);
        acc.x += self.x; acc.y += self.y; acc.z += self.z; acc.w += self.w;
        ((float4*)(g_acc + (size_t)node * HID))[lane] = acc;
    }
}

// ---------------- K3: h1 = relu(dv*acc + b1); h1@W2; scale -> hws ------------
// 4 threads/node; each loads its own quarter; 3x shfl_xor assembles the row.
__global__ void k_node2(const float* __restrict__ W2, const float* __restrict__ b1) {
    __shared__ float sW[HID * HID];
    __shared__ float sb[HID];
    if (threadIdx.x < HID * HID) sW[threadIdx.x] = W2[threadIdx.x];
    if (threadIdx.x < HID)       sb[threadIdx.x] = b1[threadIdx.x];
    __syncthreads();
    int t = blockIdx.x * blockDim.x + threadIdx.x;
    int i = t >> 2;
    if (i >= N_NODES) return;
    int q = t & 3;

    int deg = __ldg(g_pad + ((size_t)i << PAD_LOG2));
    float dv = rsqrtf((float)(deg + 1));
    float4 mine = __ldg((const float4*)(g_acc + (size_t)i * HID) + q);

    float h1[HID];
    h1[4*q+0] = fmaxf(fmaf(dv, mine.x, sb[4*q+0]), 0.0f);
    h1[4*q+1] = fmaxf(fmaf(dv, mine.y, sb[4*q+1]), 0.0f);
    h1[4*q+2] = fmaxf(fmaf(dv, mine.z, sb[4*q+2]), 0.0f);
    h1[4*q+3] = fmaxf(fmaf(dv, mine.w, sb[4*q+3]), 0.0f);
#pragma unroll
    for (int m = 1; m < 4; m++) {
        int qq = q ^ m;                        // quarter received from partner
        float4 o;
        o.x = __shfl_xor_sync(0xffffffffu, mine.x, m);
        o.y = __shfl_xor_sync(0xffffffffu, mine.y, m);
        o.z = __shfl_xor_sync(0xffffffffu, mine.z, m);
        o.w = __shfl_xor_sync(0xffffffffu, mine.w, m);
        h1[4*qq+0] = fmaxf(fmaf(dv, o.x, sb[4*qq+0]), 0.0f);
        h1[4*qq+1] = fmaxf(fmaf(dv, o.y, sb[4*qq+1]), 0.0f);
        h1[4*qq+2] = fmaxf(fmaf(dv, o.z, sb[4*qq+2]), 0.0f);
        h1[4*qq+3] = fmaxf(fmaf(dv, o.w, sb[4*qq+3]), 0.0f);
    }
    float4 r;
    float* rp = (float*)&r;
#pragma unroll
    for (int jj = 0; jj < 4; jj++) {
        int j = 4*q + jj;
        float s = 0.0f;
#pragma unroll
        for (int k = 0; k < HID; k++) s = fmaf(h1[k], sW[k*HID + j], s);
        rp[jj] = s * dv;
    }
    ((float4*)(g_hws + (size_t)i * HID))[q] = r;
}

// ---------------- K5: mean-pool; LAST block computes classifier head ---------
__global__ void k_pool(const int* __restrict__ batch, const float* __restrict__ b2,
                       const float* __restrict__ Wc, const float* __restrict__ bc,
                       float* __restrict__ out) {
    int t = blockIdx.x * blockDim.x + threadIdx.x;
    int start = t * POOL_CHUNK;
    if (start < N_NODES) {
        int end = min(start + POOL_CHUNK, N_NODES);

        float sb[HID];
#pragma unroll
        for (int j = 0; j < HID; j++) sb[j] = __ldg(b2 + j);

        float lacc[HID];
#pragma unroll
        for (int j = 0; j < HID; j++) lacc[j] = 0.0f;
        float lcnt = 0.0f;
        int cur = __ldg(batch + start);

        for (int i = start; i < end; i++) {
            int bg = __ldg(batch + i);
            if (bg != cur) {
                float* gp = g_gsum + (size_t)cur * HID;
#pragma unroll
                for (int q = 0; q < 4; q++)
                    red_add_v4(gp + 4*q, make_float4(lacc[4*q], lacc[4*q+1], lacc[4*q+2], lacc[4*q+3]));
                atomicAdd(&g_gcnt[cur], lcnt);
#pragma unroll
                for (int j = 0; j < HID; j++) lacc[j] = 0.0f;
                lcnt = 0.0f;
                cur = bg;
            }
            int deg = __ldg(g_pad + ((size_t)i << PAD_LOG2));
            float dv = rsqrtf((float)(deg + 1));
            const float4* ap = (const float4*)(g_acc + (size_t)i * HID);
#pragma unroll
            for (int q = 0; q < 4; q++) {
                float4 v = ap[q];
                lacc[4*q+0] += fmaxf(fmaf(dv, v.x, sb[4*q+0]), 0.0f);
                lacc[4*q+1] += fmaxf(fmaf(dv, v.y, sb[4*q+1]), 0.0f);
                lacc[4*q+2] += fmaxf(fmaf(dv, v.z, sb[4*q+2]), 0.0f);
                lacc[4*q+3] += fmaxf(fmaf(dv, v.w, sb[4*q+3]), 0.0f);
            }
            lcnt += 1.0f;
        }
        float* gp = g_gsum + (size_t)cur * HID;
#pragma unroll
        for (int q = 0; q < 4; q++)
            red_add_v4(gp + 4*q, make_float4(lacc[4*q], lacc[4*q+1], lacc[4*q+2], lacc[4*q+3]));
        atomicAdd(&g_gcnt[cur], lcnt);
    }

    // ---- last-block-done: classifier head ----
    __shared__ int s_last;
    __threadfence();                           // make REDs globally visible
    __syncthreads();
    if (threadIdx.x == 0)
        s_last = (atomicAdd(&g_done, 1) == POOL_BLOCKS - 1);
    __syncthreads();
    if (!s_last) return;

    __shared__ float sWc[HID * LABELS];
    __shared__ float sbc[LABELS];
    if (threadIdx.x < HID * LABELS) sWc[threadIdx.x] = __ldg(Wc + threadIdx.x);
    if (threadIdx.x < LABELS)       sbc[threadIdx.x] = __ldg(bc + threadIdx.x);
    __syncthreads();
    for (int g = threadIdx.x; g < N_GRAPHS; g += blockDim.x) {
        float inv = 1.0f / fmaxf(g_gcnt[g], 1.0f);
        float p[HID];
#pragma unroll
        for (int k = 0; k < HID; k++) p[k] = g_gsum[(size_t)g * HID + k] * inv;
#pragma unroll
        for (int l = 0; l < LABELS; l++) {
            float s = sbc[l];
#pragma unroll
            for (int k = 0; k < HID; k++) s = fmaf(p[k], sWc[k*LABELS + l], s);
            out[(size_t)g * LABELS + l] = s;
        }
        // self-clean for next replay
#pragma unroll
        for (int k = 0; k < HID; k++) g_gsum[(size_t)g * HID + k] = 0.0f;
        g_gcnt[g] = 0.0f;
    }
    if (threadIdx.x == 0) g_done = 0;          // reset for next replay
}

// ---------------- launch ------------------------------------------------------
extern "C" void kernel_launch(void* const* d_in, const int* in_sizes, int n_in,
                              void* d_out, int out_size) {
    const int*   x     = (const int*)  d_in[0];
    const int*   ei    = (const int*)  d_in[1];
    const int*   batch = (const int*)  d_in[2];
    const float* emb   = (const float*)d_in[3];
    const float* W1    = (const float*)d_in[4];
    const float* b1    = (const float*)d_in[5];
    const float* W2    = (const float*)d_in[6];
    const float* b2    = (const float*)d_in[7];
    const float* Wc    = (const float*)d_in[8];
    const float* bc    = (const float*)d_in[9];
    float* out = (float*)d_out;

    const int* src = ei;             // edge_index[0]
    const int* dst = ei + N_EDGES;   // edge_index[1]

    const int TB = 256;
    int gather_blocks = (N_NODES * 32 + TB - 1) / TB;

    k_fill  <<<(N_EDGES + TB - 1) / TB, TB>>>(src, dst, emb, W1);   // 0
    k_node1 <<<(N_NODES + TB - 1) / TB, TB>>>(x);                   // 1
    k_gather<<<gather_blocks, TB>>>();                              // 2
    k_node2 <<<(N_NODES * 4 + TB - 1) / TB, TB>>>(W2, b1);          // 3
    k_gather<<<gather_blocks, TB>>>();                              // 4
    k_pool  <<<POOL_BLOCKS, TB>>>(batch, b2, Wc, bc, out);          // 5
}

// round 17
// speedup vs baseline: 1.1202x; 1.1202x over previous
#include <cuda_runtime.h>
#include <cuda_bf16.h>

#define N_NODES  100000
#define N_EDGES  3200000
#define N_GRAPHS 512
#define VOCAB    128
#define HID      16
#define LABELS   10
#define POOL_CHUNK 8
#define PAD_LOG2 7
#define PAD      (1 << PAD_LOG2)     // max in-degree capacity (actual max ~70)

// ---------------- scratch (device globals; zero at load, self-cleaned) -------
__device__ int   g_cnt [N_NODES];            // in-degree; zeroed by k_pool
__device__ int   g_pad [(size_t)N_NODES * PAD];  // padded adjacency (src lists)
__device__ float g_t1  [VOCAB * HID];        // T1 = emb @ W1
__device__ float g_hws [N_NODES * HID];      // scaled features (gather source)
__device__ float g_acc [N_NODES * HID];      // aggregation result
__device__ float g_gsum[N_GRAPHS * HID];     // zeroed by k_out
__device__ float g_gcnt[N_GRAPHS];           // zeroed by k_out

__device__ __forceinline__ void red_add_v4(float* addr, float4 v) {
    asm volatile("red.global.add.v4.f32 [%0], {%1,%2,%3,%4};"
                 :: "l"(addr), "f"(v.x), "f"(v.y), "f"(v.z), "f"(v.w)
                 : "memory");
}

// ---------------- K0: T1 = emb @ W1 (one block, 128 threads) -----------------
__global__ void k_t1(const float* __restrict__ emb, const float* __restrict__ W1) {
    __shared__ float sW[HID * HID];
    int t = threadIdx.x;                 // 0..127 = vocab row
    sW[t] = W1[t]; sW[t + 128] = W1[t + 128];
    __syncthreads();
    float e[HID];
    const float4* ep = (const float4*)(emb + (size_t)t * HID);
#pragma unroll
    for (int q = 0; q < 4; q++) {
        float4 v = __ldg(ep + q);
        e[4*q+0] = v.x; e[4*q+1] = v.y; e[4*q+2] = v.z; e[4*q+3] = v.w;
    }
#pragma unroll
    for (int j = 0; j < HID; j++) {
        float s = 0.0f;
#pragma unroll
        for (int k = 0; k < HID; k++) s = fmaf(e[k], sW[k*HID + j], s);
        g_t1[t * HID + j] = s;
    }
}

// ---------------- K1: single-pass padded-adjacency build (1 edge/thread) -----
__global__ void k_fill(const int* __restrict__ src, const int* __restrict__ dst) {
    int e = blockIdx.x * blockDim.x + threadIdx.x;
    if (e >= N_EDGES) return;
    int s = __ldg(src + e);
    int d = __ldg(dst + e);
    int p = atomicAdd(&g_cnt[d], 1);
    if (p < PAD) g_pad[((size_t)d << PAD_LOG2) + p] = s;
}

// ---------------- K2: hws[i] = dinv_i * T1[x_i] ------------------------------
__global__ void k_node1(const int* __restrict__ x) {
    int i = blockIdx.x * blockDim.x + threadIdx.x;
    if (i >= N_NODES) return;
    float dv = rsqrtf((float)(__ldg(&g_cnt[i]) + 1));   // +1 self loop
    int xi = __ldg(x + i);
    const float4* tp = (const float4*)(g_t1 + (size_t)xi * HID);
    float4* o = (float4*)(g_hws + (size_t)i * HID);
#pragma unroll
    for (int q = 0; q < 4; q++) {
        float4 v = __ldg(tp + q);
        o[q] = make_float4(v.x * dv, v.y * dv, v.z * dv, v.w * dv);
    }
}

// ---------------- K3/K5: warp-per-node gather (R10-proven, index prefetch) ---
__global__ void k_gather() {
    int node = (blockIdx.x * blockDim.x + threadIdx.x) >> 5;
    if (node >= N_NODES) return;
    int lane = threadIdx.x & 31;
    int q = lane & 3;                          // quarter of feature row (float4)
    int cnt = __ldg(&g_cnt[node]);
    if (cnt > PAD) cnt = PAD;
    const int* adj = g_pad + ((size_t)node << PAD_LOG2);

    float4 acc = make_float4(0.f, 0.f, 0.f, 0.f);
    int p = lane >> 2;
    int s_cur = (p < cnt) ? __ldg(adj + p) : 0;
    while (p < cnt) {
        int pn = p + 8;
        int s_nxt = (pn < cnt) ? __ldg(adj + pn) : 0;   // prefetch next index
        float4 v = __ldg((const float4*)(g_hws + (size_t)s_cur * HID) + q);
        acc.x += v.x; acc.y += v.y; acc.z += v.z; acc.w += v.w;
        p = pn; s_cur = s_nxt;
    }
#pragma unroll
    for (int off = 4; off < 32; off <<= 1) {
        acc.x += __shfl_xor_sync(0xffffffffu, acc.x, off);
        acc.y += __shfl_xor_sync(0xffffffffu, acc.y, off);
        acc.z += __shfl_xor_sync(0xffffffffu, acc.z, off);
        acc.w += __shfl_xor_sync(0xffffffffu, acc.w, off);
    }
    if (lane < 4) {                            // lane == q
        float4 self = __ldg((const float4*)(g_hws + (size_t)node * HID) + lane);
        acc.x += self.x; acc.y += self.y; acc.z += self.z; acc.w += self.w;
        ((float4*)(g_acc + (size_t)node * HID))[lane] = acc;
    }
}

// ---------------- K4: h1 = relu(dv*acc + b1); h1@W2; scale -> hws ------------
// 4 threads per node: thread handles quarter q of node i.
__global__ void k_node2(const float* __restrict__ W2, const float* __restrict__ b1) {
    __shared__ float sW[HID * HID];
    __shared__ float sb[HID];
    if (threadIdx.x < HID * HID) sW[threadIdx.x] = W2[threadIdx.x];
    if (threadIdx.x < HID)       sb[threadIdx.x] = b1[threadIdx.x];
    __syncthreads();
    int t = blockIdx.x * blockDim.x + threadIdx.x;
    int i = t >> 2;
    if (i >= N_NODES) return;
    int q = t & 3;

    float dv = rsqrtf((float)(__ldg(&g_cnt[i]) + 1));
    float h1[HID];
    const float4* ap = (const float4*)(g_acc + (size_t)i * HID);
#pragma unroll
    for (int qq = 0; qq < 4; qq++) {
        float4 v = __ldg(ap + qq);
        h1[4*qq+0] = fmaxf(fmaf(dv, v.x, sb[4*qq+0]), 0.0f);
        h1[4*qq+1] = fmaxf(fmaf(dv, v.y, sb[4*qq+1]), 0.0f);
        h1[4*qq+2] = fmaxf(fmaf(dv, v.z, sb[4*qq+2]), 0.0f);
        h1[4*qq+3] = fmaxf(fmaf(dv, v.w, sb[4*qq+3]), 0.0f);
    }
    float4 r;
    float* rp = (float*)&r;
#pragma unroll
    for (int jj = 0; jj < 4; jj++) {
        int j = 4*q + jj;
        float s = 0.0f;
#pragma unroll
        for (int k = 0; k < HID; k++) s = fmaf(h1[k], sW[k*HID + j], s);
        rp[jj] = s * dv;
    }
    ((float4*)(g_hws + (size_t)i * HID))[q] = r;
}

// ---------------- K6: h2 = relu(dv*acc + b2); mean-pool (run-aggregated) -----
__global__ void k_pool(const int* __restrict__ batch, const float* __restrict__ b2) {
    int t = blockIdx.x * blockDim.x + threadIdx.x;
    int start = t * POOL_CHUNK;
    if (start >= N_NODES) return;
    int end = min(start + POOL_CHUNK, N_NODES);

    float sb[HID];
#pragma unroll
    for (int j = 0; j < HID; j++) sb[j] = __ldg(b2 + j);

    float lacc[HID];
#pragma unroll
    for (int j = 0; j < HID; j++) lacc[j] = 0.0f;
    float lcnt = 0.0f;
    int cur = __ldg(batch + start);

    for (int i = start; i < end; i++) {
        int bg = __ldg(batch + i);
        if (bg != cur) {
            float* gp = g_gsum + (size_t)cur * HID;
#pragma unroll
            for (int q = 0; q < 4; q++)
                red_add_v4(gp + 4*q, make_float4(lacc[4*q], lacc[4*q+1], lacc[4*q+2], lacc[4*q+3]));
            atomicAdd(&g_gcnt[cur], lcnt);
#pragma unroll
            for (int j = 0; j < HID; j++) lacc[j] = 0.0f;
            lcnt = 0.0f;
            cur = bg;
        }
        float dv = rsqrtf((float)(g_cnt[i] + 1));
        const float4* ap = (const float4*)(g_acc + (size_t)i * HID);
#pragma unroll
        for (int q = 0; q < 4; q++) {
            float4 v = ap[q];
            lacc[4*q+0] += fmaxf(fmaf(dv, v.x, sb[4*q+0]), 0.0f);
            lacc[4*q+1] += fmaxf(fmaf(dv, v.y, sb[4*q+1]), 0.0f);
            lacc[4*q+2] += fmaxf(fmaf(dv, v.z, sb[4*q+2]), 0.0f);
            lacc[4*q+3] += fmaxf(fmaf(dv, v.w, sb[4*q+3]), 0.0f);
        }
        lcnt += 1.0f;
        g_cnt[i] = 0;                          // self-clean for next replay
    }
    float* gp = g_gsum + (size_t)cur * HID;
#pragma unroll
    for (int q = 0; q < 4; q++)
        red_add_v4(gp + 4*q, make_float4(lacc[4*q], lacc[4*q+1], lacc[4*q+2], lacc[4*q+3]));
    atomicAdd(&g_gcnt[cur], lcnt);
}

// ---------------- K7: classifier head + self-clean of pool buffers -----------
__global__ void k_out(const float* __restrict__ Wc, const float* __restrict__ bc,
                      float* __restrict__ out) {
    __shared__ float sW[HID * LABELS];
    __shared__ float sb[LABELS];
    if (threadIdx.x < HID * LABELS) sW[threadIdx.x] = Wc[threadIdx.x];
    if (threadIdx.x < LABELS)       sb[threadIdx.x] = bc[threadIdx.x];
    __syncthreads();
    int g = blockIdx.x * blockDim.x + threadIdx.x;
    if (g >= N_GRAPHS) return;

    float inv = 1.0f / fmaxf(g_gcnt[g], 1.0f);
    float p[HID];
#pragma unroll
    for (int k = 0; k < HID; k++) p[k] = g_gsum[(size_t)g * HID + k] * inv;
#pragma unroll
    for (int l = 0; l < LABELS; l++) {
        float s = sb[l];
#pragma unroll
        for (int k = 0; k < HID; k++) s = fmaf(p[k], sW[k*LABELS + l], s);
        out[(size_t)g * LABELS + l] = s;
    }
    // self-clean for next replay
#pragma unroll
    for (int k = 0; k < HID; k++) g_gsum[(size_t)g * HID + k] = 0.0f;
    g_gcnt[g] = 0.0f;
}

// ---------------- launch ------------------------------------------------------
extern "C" void kernel_launch(void* const* d_in, const int* in_sizes, int n_in,
                              void* d_out, int out_size) {
    const int*   x     = (const int*)  d_in[0];
    const int*   ei    = (const int*)  d_in[1];
    const int*   batch = (const int*)  d_in[2];
    const float* emb   = (const float*)d_in[3];
    const float* W1    = (const float*)d_in[4];
    const float* b1    = (const float*)d_in[5];
    const float* W2    = (const float*)d_in[6];
    const float* b2    = (const float*)d_in[7];
    const float* Wc    = (const float*)d_in[8];
    const float* bc    = (const float*)d_in[9];
    float* out = (float*)d_out;

    const int* src = ei;             // edge_index[0]
    const int* dst = ei + N_EDGES;   // edge_index[1]

    const int TB = 256;
    int gather_blocks = (N_NODES * 32 + TB - 1) / TB;
    int pool_threads = (N_NODES + POOL_CHUNK - 1) / POOL_CHUNK;

    k_t1    <<<1, 128>>>(emb, W1);                              // 0
    k_fill  <<<(N_EDGES + TB - 1) / TB, TB>>>(src, dst);        // 1
    k_node1 <<<(N_NODES + TB - 1) / TB, TB>>>(x);               // 2
    k_gather<<<gather_blocks, TB>>>();                          // 3
    k_node2 <<<(N_NODES * 4 + TB - 1) / TB, TB>>>(W2, b1);      // 4
    k_gather<<<gather_blocks, TB>>>();                          // 5  <- ncu
    k_pool  <<<(pool_threads + TB - 1) / TB, TB>>>(batch, b2);  // 6
    k_out   <<<(N_GRAPHS + TB - 1) / TB, TB>>>(Wc, bc, out);    // 7
}